// round 6
// baseline (speedup 1.0000x reference)
#include <cuda_runtime.h>
#include <math.h>

#define BB 2
#define LL 384
#define DD 256
#define HH 8
#define DHH 32

// Scratch (device globals — no allocation allowed). 16B-aligned: float4 access.
__device__ __align__(16) float g_KP[BB*HH*LL*DHH];   // [b][h][l][dh]
__device__ __align__(16) float g_VP[BB*HH*LL*DHH];   // [b][h][l][dh]
__device__ __align__(16) float g_QU[BB*LL*DD];       // [b][l][h*32+dh]  (q + u)
__device__ __align__(16) float g_QV[BB*LL*DD];       // [b][l][h*32+dh]  (q + v)
__device__ __align__(16) float g_W [BB*LL*HH*DD];    // [b][q][h][d]

// ---------------------------------------------------------------------------
// Kernel 1: fused Q/K/V projections.  out = X @ W.T + b  (M=768, N=256, K=256)
// 32x64 tile, K-chunk 64, 256 threads, 2x4 per thread. grid (24, 4, 3)
// ---------------------------------------------------------------------------
__global__ void __launch_bounds__(256) proj_kernel(
    const float* __restrict__ key,   const float* __restrict__ query,
    const float* __restrict__ value,
    const float* __restrict__ Wk, const float* __restrict__ bk,
    const float* __restrict__ Wq, const float* __restrict__ bq,
    const float* __restrict__ Wv, const float* __restrict__ bv,
    const float* __restrict__ u,  const float* __restrict__ vvec)
{
    const int z = blockIdx.z;
    const float* X    = (z == 0) ? key : (z == 1) ? query : value;
    const float* Wt   = (z == 0) ? Wk  : (z == 1) ? Wq    : Wv;
    const float* bias = (z == 0) ? bk  : (z == 1) ? bq    : bv;

    const int m0 = blockIdx.x * 32;
    const int n0 = blockIdx.y * 64;
    const int tid = threadIdx.x;
    const int tx = tid % 16, ty = tid / 16;   // tx: n/4, ty: 0..15

    __shared__ float a_sm[32 * 65];   // [row][k]  (scalar reads only)
    __shared__ float b_sm[64 * 68];   // [k][col]  stride 68 -> 16B-aligned float4

    float acc[2][4] = {};

    const int lr = tid / 16;          // 0..15
    const int lc = (tid % 16) * 4;    // 0..60

    for (int kt = 0; kt < DD; kt += 64) {
        // A tile: 32 rows x 64 k (2 float4 per thread)
        {
            float4 va = *(const float4*)(X + (m0 + lr) * DD + kt + lc);
            float* d0 = a_sm + lr * 65 + lc;
            d0[0] = va.x; d0[1] = va.y; d0[2] = va.z; d0[3] = va.w;
            float4 vb = *(const float4*)(X + (m0 + lr + 16) * DD + kt + lc);
            float* d1 = a_sm + (lr + 16) * 65 + lc;
            d1[0] = vb.x; d1[1] = vb.y; d1[2] = vb.z; d1[3] = vb.w;
        }
        // B tile: 64 n-rows x 64 k, transposed into [k][n] (4 float4 per thread)
        #pragma unroll
        for (int j = 0; j < 4; j++) {
            int nr = lr + 16 * j;
            float4 vb = *(const float4*)(Wt + (n0 + nr) * DD + kt + lc);
            b_sm[(lc + 0) * 68 + nr] = vb.x;
            b_sm[(lc + 1) * 68 + nr] = vb.y;
            b_sm[(lc + 2) * 68 + nr] = vb.z;
            b_sm[(lc + 3) * 68 + nr] = vb.w;
        }
        __syncthreads();
        #pragma unroll
        for (int k = 0; k < 64; k++) {
            float a0 = a_sm[ty * 65 + k];
            float a1 = a_sm[(ty + 16) * 65 + k];
            float4 bf = *(const float4*)(b_sm + k * 68 + tx * 4);
            acc[0][0] += a0 * bf.x; acc[0][1] += a0 * bf.y; acc[0][2] += a0 * bf.z; acc[0][3] += a0 * bf.w;
            acc[1][0] += a1 * bf.x; acc[1][1] += a1 * bf.y; acc[1][2] += a1 * bf.z; acc[1][3] += a1 * bf.w;
        }
        __syncthreads();
    }

    #pragma unroll
    for (int i = 0; i < 2; i++) {
        int m = m0 + ty + 16 * i;
        int b = m / LL, l = m % LL;
        #pragma unroll
        for (int j = 0; j < 4; j++) {
            int jc = n0 + tx * 4 + j;
            float val = acc[i][j] + bias[jc];
            int h = jc / DHH, dh = jc % DHH;
            if (z == 0) {
                g_KP[((b * HH + h) * LL + l) * DHH + dh] = val;
            } else if (z == 2) {
                g_VP[((b * HH + h) * LL + l) * DHH + dh] = val;
            } else {
                g_QU[m * DD + jc] = val + u[jc];
                g_QV[m * DD + jc] = val + vvec[jc];
            }
        }
    }
}

// ---------------------------------------------------------------------------
// Kernel 2: W[b,q,h,:] = sum_dh QV[b,q,h,dh] * Wr[h*32+dh, :]
// per-head GEMM [768 x 32] @ [32 x 256]. 64x64 tile. grid (12, 4, 8)
// ---------------------------------------------------------------------------
__global__ void __launch_bounds__(256) w_kernel(const float* __restrict__ Wr)
{
    const int h  = blockIdx.z;
    const int m0 = blockIdx.x * 64;   // bq tile
    const int n0 = blockIdx.y * 64;   // d tile
    const int tid = threadIdx.x;
    const int tx = tid % 16, ty = tid / 16;

    __shared__ float a_sm[64 * 33];   // [row][k]  (scalar reads)
    __shared__ float b_sm[32 * 68];   // [k][col]

    {
        int r = tid / 4, cb = (tid % 4) * 8;
        #pragma unroll
        for (int cc = 0; cc < 8; cc += 4) {
            float4 va = *(const float4*)(g_QV + (m0 + r) * DD + h * DHH + cb + cc);
            float* dst = a_sm + r * 33 + cb + cc;
            dst[0] = va.x; dst[1] = va.y; dst[2] = va.z; dst[3] = va.w;
        }
    }
    {
        int k = tid / 8, cb = (tid % 8) * 8;
        #pragma unroll
        for (int cc = 0; cc < 8; cc += 4) {
            float4 vb = *(const float4*)(Wr + (h * DHH + k) * DD + n0 + cb + cc);
            *(float4*)(b_sm + k * 68 + cb + cc) = vb;
        }
    }
    __syncthreads();

    float acc[4][4] = {};
    #pragma unroll
    for (int k = 0; k < 32; k++) {
        float a0 = a_sm[(ty * 4 + 0) * 33 + k];
        float a1 = a_sm[(ty * 4 + 1) * 33 + k];
        float a2 = a_sm[(ty * 4 + 2) * 33 + k];
        float a3 = a_sm[(ty * 4 + 3) * 33 + k];
        float4 bf = *(const float4*)(b_sm + k * 68 + tx * 4);
        acc[0][0] += a0 * bf.x; acc[0][1] += a0 * bf.y; acc[0][2] += a0 * bf.z; acc[0][3] += a0 * bf.w;
        acc[1][0] += a1 * bf.x; acc[1][1] += a1 * bf.y; acc[1][2] += a1 * bf.z; acc[1][3] += a1 * bf.w;
        acc[2][0] += a2 * bf.x; acc[2][1] += a2 * bf.y; acc[2][2] += a2 * bf.z; acc[2][3] += a2 * bf.w;
        acc[3][0] += a3 * bf.x; acc[3][1] += a3 * bf.y; acc[3][2] += a3 * bf.z; acc[3][3] += a3 * bf.w;
    }

    #pragma unroll
    for (int i = 0; i < 4; i++) {
        int bq = m0 + ty * 4 + i;
        #pragma unroll
        for (int j = 0; j < 4; j++) {
            g_W[((size_t)bq * HH + h) * DD + n0 + tx * 4 + j] = acc[i][j];
        }
    }
}

// ---------------------------------------------------------------------------
// Kernel 3: attention. One block per (q, b), warp = head.
// Lane split: kk = lane/8 (4 k-rows per warp-iter), dd = lane%8 (d chunk).
// 3-shfl (8-lane) reduction instead of 5-shfl (32-lane) per k.
// ---------------------------------------------------------------------------
__global__ void __launch_bounds__(256) attn_kernel(
    const float* __restrict__ pos,
    const float* __restrict__ key_mask,
    const float* __restrict__ br,
    float* __restrict__ out)
{
    const int q = blockIdx.x, b = blockIdx.y;
    const int tid = threadIdx.x;
    const int h = tid / 32, lane = tid % 32;
    const int kk = lane >> 3, dd = lane & 7;

    __shared__ float sc[HH][LL];
    __shared__ float pm[LL];

    for (int k = tid; k < LL; k += 256)
        pm[k] = (1.0f - key_mask[b * LL + k]) * 1e15f;

    // W slice for this (b,q,h): lane dd owns d in {32i + 4dd .. 32i + 4dd+3}, i=0..7
    const float* wrow = g_W + (((size_t)(b * LL + q)) * HH + h) * DD;
    float4 w[8];
    #pragma unroll
    for (int i = 0; i < 8; i++)
        w[i] = *(const float4*)(wrow + i * 32 + dd * 4);

    const float4 qu4 = *(const float4*)(g_QU + (b * LL + q) * DD + h * DHH + dd * 4);
    const float4 qv4 = *(const float4*)(g_QV + (b * LL + q) * DD + h * DHH + dd * 4);
    const float4 br4 = *(const float4*)(br + h * DHH + dd * 4);

    // ccp = (q+v) . br  (8-lane reduce covers all 32 dh)
    float ccp = qv4.x * br4.x + qv4.y * br4.y + qv4.z * br4.z + qv4.w * br4.w;
    ccp += __shfl_xor_sync(0xffffffffu, ccp, 4);
    ccp += __shfl_xor_sync(0xffffffffu, ccp, 2);
    ccp += __shfl_xor_sync(0xffffffffu, ccp, 1);

    const float scale = 0.17677669529663687f;  // 1/sqrt(32)
    const float* posb = pos + ((size_t)(b * LL + q)) * LL * DD;
    const float* kpb  = g_KP + ((size_t)(b * HH + h)) * LL * DHH;
    __syncthreads();

    // scores: B_D (pos . W) + A_C (kp . qu), 4 k-rows per warp iteration
    #pragma unroll 2
    for (int k0 = 0; k0 < LL; k0 += 4) {
        const int k = k0 + kk;
        const float* pr = posb + (size_t)k * DD;
        float4 kp4 = *(const float4*)(kpb + k * DHH + dd * 4);
        float part = kp4.x * qu4.x + kp4.y * qu4.y + kp4.z * qu4.z + kp4.w * qu4.w;
        #pragma unroll
        for (int i = 0; i < 8; i++) {
            float4 p = *(const float4*)(pr + i * 32 + dd * 4);
            part += p.x * w[i].x + p.y * w[i].y + p.z * w[i].z + p.w * w[i].w;
        }
        part += __shfl_xor_sync(0xffffffffu, part, 4);
        part += __shfl_xor_sync(0xffffffffu, part, 2);
        part += __shfl_xor_sync(0xffffffffu, part, 1);
        if (dd == 0)
            sc[h][k] = (part + ccp) * scale - pm[k];
    }
    __syncwarp();

    // softmax over k (warp-private row)
    float m = -1e30f;
    for (int k = lane; k < LL; k += 32) m = fmaxf(m, sc[h][k]);
    #pragma unroll
    for (int off = 16; off; off >>= 1)
        m = fmaxf(m, __shfl_xor_sync(0xffffffffu, m, off));
    float s = 0.0f;
    for (int k = lane; k < LL; k += 32) {
        float e = __expf(sc[h][k] - m);
        sc[h][k] = e;
        s += e;
    }
    #pragma unroll
    for (int off = 16; off; off >>= 1)
        s += __shfl_xor_sync(0xffffffffu, s, off);
    const float rinv = 1.0f / s;
    __syncwarp();

    // out = attn @ V  (lane = dh, coalesced)
    float acc = 0.0f;
    const float* vp = g_VP + ((size_t)(b * HH + h)) * LL * DHH + lane;
    #pragma unroll 4
    for (int k = 0; k < LL; k++)
        acc += sc[h][k] * vp[k * DHH];

    out[(b * LL + q) * DD + h * DHH + lane] = acc * rinv;
}

// ---------------------------------------------------------------------------
extern "C" void kernel_launch(void* const* d_in, const int* in_sizes, int n_in,
                              void* d_out, int out_size)
{
    const float* key      = (const float*)d_in[0];
    const float* query    = (const float*)d_in[1];
    const float* value    = (const float*)d_in[2];
    const float* pos      = (const float*)d_in[3];
    const float* key_mask = (const float*)d_in[4];
    const float* Wk = (const float*)d_in[5];
    const float* bk = (const float*)d_in[6];
    const float* Wq = (const float*)d_in[7];
    const float* bq = (const float*)d_in[8];
    const float* Wv = (const float*)d_in[9];
    const float* bv = (const float*)d_in[10];
    const float* Wr = (const float*)d_in[11];
    const float* br = (const float*)d_in[12];
    const float* u  = (const float*)d_in[13];
    const float* v  = (const float*)d_in[14];
    float* out = (float*)d_out;

    proj_kernel<<<dim3(24, 4, 3), 256>>>(key, query, value, Wk, bk, Wq, bq, Wv, bv, u, v);
    w_kernel<<<dim3(12, 4, 8), 256>>>(Wr);
    attn_kernel<<<dim3(LL, BB), 256>>>(pos, key_mask, br, out);
}

// round 10
// speedup vs baseline: 1.3531x; 1.3531x over previous
#include <cuda_runtime.h>
#include <math.h>

#define BB 2
#define LL 384
#define DD 256
#define HH 8
#define DHH 32

// Scratch (device globals — no allocation allowed). 16B-aligned: float4 access.
__device__ __align__(16) float g_KP[BB*HH*LL*DHH];   // [b][h][l][dh]
__device__ __align__(16) float g_VP[BB*HH*LL*DHH];   // [b][h][l][dh]
__device__ __align__(16) float g_QU[BB*LL*DD];       // [b][l][h*32+dh]  (q + u)
__device__ __align__(16) float g_QV[BB*LL*DD];       // [b][l][h*32+dh]  (q + v)
__device__ __align__(16) float g_W [BB*LL*HH*DD];    // [b][q][h][d]

// ---------------------------------------------------------------------------
// Kernel 1: fused Q/K/V projections.  out = X @ W.T + b  (M=768, N=256, K=256)
// ---------------------------------------------------------------------------
__global__ void __launch_bounds__(256) proj_kernel(
    const float* __restrict__ key,   const float* __restrict__ query,
    const float* __restrict__ value,
    const float* __restrict__ Wk, const float* __restrict__ bk,
    const float* __restrict__ Wq, const float* __restrict__ bq,
    const float* __restrict__ Wv, const float* __restrict__ bv,
    const float* __restrict__ u,  const float* __restrict__ vvec)
{
    const int z = blockIdx.z;
    const float* X    = (z == 0) ? key : (z == 1) ? query : value;
    const float* Wt   = (z == 0) ? Wk  : (z == 1) ? Wq    : Wv;
    const float* bias = (z == 0) ? bk  : (z == 1) ? bq    : bv;

    const int m0 = blockIdx.x * 32;
    const int n0 = blockIdx.y * 64;
    const int tid = threadIdx.x;
    const int tx = tid % 16, ty = tid / 16;

    __shared__ float a_sm[32 * 65];   // [row][k]  (scalar reads only)
    __shared__ float b_sm[64 * 68];   // [k][col]  stride 68 -> 16B-aligned float4

    float acc[2][4] = {};

    const int lr = tid / 16;
    const int lc = (tid % 16) * 4;

    for (int kt = 0; kt < DD; kt += 64) {
        {
            float4 va = *(const float4*)(X + (m0 + lr) * DD + kt + lc);
            float* d0 = a_sm + lr * 65 + lc;
            d0[0] = va.x; d0[1] = va.y; d0[2] = va.z; d0[3] = va.w;
            float4 vb = *(const float4*)(X + (m0 + lr + 16) * DD + kt + lc);
            float* d1 = a_sm + (lr + 16) * 65 + lc;
            d1[0] = vb.x; d1[1] = vb.y; d1[2] = vb.z; d1[3] = vb.w;
        }
        #pragma unroll
        for (int j = 0; j < 4; j++) {
            int nr = lr + 16 * j;
            float4 vb = *(const float4*)(Wt + (n0 + nr) * DD + kt + lc);
            b_sm[(lc + 0) * 68 + nr] = vb.x;
            b_sm[(lc + 1) * 68 + nr] = vb.y;
            b_sm[(lc + 2) * 68 + nr] = vb.z;
            b_sm[(lc + 3) * 68 + nr] = vb.w;
        }
        __syncthreads();
        #pragma unroll
        for (int k = 0; k < 64; k++) {
            float a0 = a_sm[ty * 65 + k];
            float a1 = a_sm[(ty + 16) * 65 + k];
            float4 bf = *(const float4*)(b_sm + k * 68 + tx * 4);
            acc[0][0] += a0 * bf.x; acc[0][1] += a0 * bf.y; acc[0][2] += a0 * bf.z; acc[0][3] += a0 * bf.w;
            acc[1][0] += a1 * bf.x; acc[1][1] += a1 * bf.y; acc[1][2] += a1 * bf.z; acc[1][3] += a1 * bf.w;
        }
        __syncthreads();
    }

    #pragma unroll
    for (int i = 0; i < 2; i++) {
        int m = m0 + ty + 16 * i;
        int b = m / LL, l = m % LL;
        #pragma unroll
        for (int j = 0; j < 4; j++) {
            int jc = n0 + tx * 4 + j;
            float val = acc[i][j] + bias[jc];
            int h = jc / DHH, dh = jc % DHH;
            if (z == 0) {
                g_KP[((b * HH + h) * LL + l) * DHH + dh] = val;
            } else if (z == 2) {
                g_VP[((b * HH + h) * LL + l) * DHH + dh] = val;
            } else {
                g_QU[m * DD + jc] = val + u[jc];
                g_QV[m * DD + jc] = val + vvec[jc];
            }
        }
    }
}

// ---------------------------------------------------------------------------
// Kernel 2: W[b,q,h,:] = sum_dh QV[b,q,h,dh] * Wr[h*32+dh, :]
// ---------------------------------------------------------------------------
__global__ void __launch_bounds__(256) w_kernel(const float* __restrict__ Wr)
{
    const int h  = blockIdx.z;
    const int m0 = blockIdx.x * 64;
    const int n0 = blockIdx.y * 64;
    const int tid = threadIdx.x;
    const int tx = tid % 16, ty = tid / 16;

    __shared__ float a_sm[64 * 33];
    __shared__ float b_sm[32 * 68];

    {
        int r = tid / 4, cb = (tid % 4) * 8;
        #pragma unroll
        for (int cc = 0; cc < 8; cc += 4) {
            float4 va = *(const float4*)(g_QV + (m0 + r) * DD + h * DHH + cb + cc);
            float* dst = a_sm + r * 33 + cb + cc;
            dst[0] = va.x; dst[1] = va.y; dst[2] = va.z; dst[3] = va.w;
        }
    }
    {
        int k = tid / 8, cb = (tid % 8) * 8;
        #pragma unroll
        for (int cc = 0; cc < 8; cc += 4) {
            float4 vb = *(const float4*)(Wr + (h * DHH + k) * DD + n0 + cb + cc);
            *(float4*)(b_sm + k * 68 + cb + cc) = vb;
        }
    }
    __syncthreads();

    float acc[4][4] = {};
    #pragma unroll
    for (int k = 0; k < 32; k++) {
        float a0 = a_sm[(ty * 4 + 0) * 33 + k];
        float a1 = a_sm[(ty * 4 + 1) * 33 + k];
        float a2 = a_sm[(ty * 4 + 2) * 33 + k];
        float a3 = a_sm[(ty * 4 + 3) * 33 + k];
        float4 bf = *(const float4*)(b_sm + k * 68 + tx * 4);
        acc[0][0] += a0 * bf.x; acc[0][1] += a0 * bf.y; acc[0][2] += a0 * bf.z; acc[0][3] += a0 * bf.w;
        acc[1][0] += a1 * bf.x; acc[1][1] += a1 * bf.y; acc[1][2] += a1 * bf.z; acc[1][3] += a1 * bf.w;
        acc[2][0] += a2 * bf.x; acc[2][1] += a2 * bf.y; acc[2][2] += a2 * bf.z; acc[2][3] += a2 * bf.w;
        acc[3][0] += a3 * bf.x; acc[3][1] += a3 * bf.y; acc[3][2] += a3 * bf.z; acc[3][3] += a3 * bf.w;
    }

    #pragma unroll
    for (int i = 0; i < 4; i++) {
        int bq = m0 + ty * 4 + i;
        #pragma unroll
        for (int j = 0; j < 4; j++) {
            g_W[((size_t)bq * HH + h) * DD + n0 + tx * 4 + j] = acc[i][j];
        }
    }
}

// ---------------------------------------------------------------------------
// Kernel 3: attention. Block per (q,b), warp = head.
// 4 k-rows per warp-iter (kk = lane/8), dd = lane%8 owns 4-float d-chunks.
// W slice lives in SMEM (broadcast LDS.128) -> low register pressure, no spills.
// ---------------------------------------------------------------------------
__global__ void __launch_bounds__(256, 3) attn_kernel(
    const float* __restrict__ pos,
    const float* __restrict__ key_mask,
    const float* __restrict__ br,
    float* __restrict__ out)
{
    const int q = blockIdx.x, b = blockIdx.y;
    const int tid = threadIdx.x;
    const int h = tid >> 5, lane = tid & 31;
    const int kk = lane >> 3, dd = lane & 7;

    __shared__ float sc[HH][LL];
    __shared__ float pm[LL];
    __shared__ __align__(16) float w_sm[HH][DD];   // 8 KB

    // Load W for this (b,q): 2 float4 per thread, coalesced.
    {
        const float4* src = (const float4*)(g_W + ((size_t)(b * LL + q)) * HH * DD);
        float4* dst = (float4*)&w_sm[0][0];
        dst[tid]       = src[tid];
        dst[tid + 256] = src[tid + 256];
    }
    for (int k = tid; k < LL; k += 256)
        pm[k] = (1.0f - key_mask[b * LL + k]) * 1e15f;

    const float4 qu4 = *(const float4*)(g_QU + (b * LL + q) * DD + h * DHH + dd * 4);
    const float4 qv4 = *(const float4*)(g_QV + (b * LL + q) * DD + h * DHH + dd * 4);
    const float4 br4 = *(const float4*)(br + h * DHH + dd * 4);

    // ccp = (q+v) . br  (8-lane reduce covers all 32 dh)
    float ccp = qv4.x * br4.x + qv4.y * br4.y + qv4.z * br4.z + qv4.w * br4.w;
    ccp += __shfl_xor_sync(0xffffffffu, ccp, 4);
    ccp += __shfl_xor_sync(0xffffffffu, ccp, 2);
    ccp += __shfl_xor_sync(0xffffffffu, ccp, 1);

    const float scale = 0.17677669529663687f;  // 1/sqrt(32)
    const float* posb = pos + ((size_t)(b * LL + q)) * LL * DD;
    const float* kpb  = g_KP + ((size_t)(b * HH + h)) * LL * DHH;
    __syncthreads();

    // scores: B_D (pos . W) + A_C (kp . qu), 4 k-rows per warp iteration
    #pragma unroll 2
    for (int k0 = 0; k0 < LL; k0 += 4) {
        const int k = k0 + kk;
        const float* pr = posb + (size_t)k * DD;
        float4 kp4 = *(const float4*)(kpb + k * DHH + dd * 4);
        float part = kp4.x * qu4.x + kp4.y * qu4.y + kp4.z * qu4.z + kp4.w * qu4.w;
        #pragma unroll
        for (int i = 0; i < 8; i++) {
            float4 p  = *(const float4*)(pr + i * 32 + dd * 4);
            float4 wv = *(const float4*)(&w_sm[h][i * 32 + dd * 4]);
            part += p.x * wv.x + p.y * wv.y + p.z * wv.z + p.w * wv.w;
        }
        part += __shfl_xor_sync(0xffffffffu, part, 4);
        part += __shfl_xor_sync(0xffffffffu, part, 2);
        part += __shfl_xor_sync(0xffffffffu, part, 1);
        if (dd == 0)
            sc[h][k] = (part + ccp) * scale - pm[k];
    }
    __syncwarp();

    // softmax over k (warp-private row)
    float m = -1e30f;
    for (int k = lane; k < LL; k += 32) m = fmaxf(m, sc[h][k]);
    #pragma unroll
    for (int off = 16; off; off >>= 1)
        m = fmaxf(m, __shfl_xor_sync(0xffffffffu, m, off));
    float s = 0.0f;
    for (int k = lane; k < LL; k += 32) {
        float e = __expf(sc[h][k] - m);
        sc[h][k] = e;
        s += e;
    }
    #pragma unroll
    for (int off = 16; off; off >>= 1)
        s += __shfl_xor_sync(0xffffffffu, s, off);
    const float rinv = 1.0f / s;
    __syncwarp();

    // out = attn @ V  (lane = dh, coalesced)
    float acc = 0.0f;
    const float* vp = g_VP + ((size_t)(b * HH + h)) * LL * DHH + lane;
    #pragma unroll 4
    for (int k = 0; k < LL; k++)
        acc += sc[h][k] * vp[k * DHH];

    out[(b * LL + q) * DD + h * DHH + lane] = acc * rinv;
}

// ---------------------------------------------------------------------------
extern "C" void kernel_launch(void* const* d_in, const int* in_sizes, int n_in,
                              void* d_out, int out_size)
{
    const float* key      = (const float*)d_in[0];
    const float* query    = (const float*)d_in[1];
    const float* value    = (const float*)d_in[2];
    const float* pos      = (const float*)d_in[3];
    const float* key_mask = (const float*)d_in[4];
    const float* Wk = (const float*)d_in[5];
    const float* bk = (const float*)d_in[6];
    const float* Wq = (const float*)d_in[7];
    const float* bq = (const float*)d_in[8];
    const float* Wv = (const float*)d_in[9];
    const float* bv = (const float*)d_in[10];
    const float* Wr = (const float*)d_in[11];
    const float* br = (const float*)d_in[12];
    const float* u  = (const float*)d_in[13];
    const float* v  = (const float*)d_in[14];
    float* out = (float*)d_out;

    proj_kernel<<<dim3(24, 4, 3), 256>>>(key, query, value, Wk, bk, Wq, bq, Wv, bv, u, v);
    w_kernel<<<dim3(12, 4, 8), 256>>>(Wr);
    attn_kernel<<<dim3(LL, BB), 256>>>(pos, key_mask, br, out);
}

// round 11
// speedup vs baseline: 1.8361x; 1.3570x over previous
#include <cuda_runtime.h>
#include <math.h>
#include <stdint.h>

#define BB 2
#define LL 384
#define DD 256
#define HH 8
#define DHH 32
#define KT 32               // k-rows per pos tile
#define NT (LL/KT)          // 12 tiles
#define PSTR 260            // padded pos row stride in floats (65 float4, conflict-free)

// Scratch (device globals — no allocation allowed). 16B-aligned: float4 access.
__device__ __align__(16) float g_KP[BB*HH*LL*DHH];   // [b][h][l][dh]
__device__ __align__(16) float g_VP[BB*HH*LL*DHH];   // [b][h][l][dh]
__device__ __align__(16) float g_QU[BB*LL*DD];       // [b][l][h*32+dh]  (q + u)
__device__ __align__(16) float g_QV[BB*LL*DD];       // [b][l][h*32+dh]  (q + v)
__device__ __align__(16) float g_W [BB*LL*HH*DD];    // [b][q][h][d]
__device__ __align__(16) float g_AC[BB*HH*LL*LL];    // [b][h][q][k]  content term A+C

// ---------------------------------------------------------------------------
// Kernel 1: fused Q/K/V projections.  out = X @ W.T + b  (M=768, N=256, K=256)
// ---------------------------------------------------------------------------
__global__ void __launch_bounds__(256) proj_kernel(
    const float* __restrict__ key,   const float* __restrict__ query,
    const float* __restrict__ value,
    const float* __restrict__ Wk, const float* __restrict__ bk,
    const float* __restrict__ Wq, const float* __restrict__ bq,
    const float* __restrict__ Wv, const float* __restrict__ bv,
    const float* __restrict__ u,  const float* __restrict__ vvec)
{
    const int z = blockIdx.z;
    const float* X    = (z == 0) ? key : (z == 1) ? query : value;
    const float* Wt   = (z == 0) ? Wk  : (z == 1) ? Wq    : Wv;
    const float* bias = (z == 0) ? bk  : (z == 1) ? bq    : bv;

    const int m0 = blockIdx.x * 32;
    const int n0 = blockIdx.y * 64;
    const int tid = threadIdx.x;
    const int tx = tid % 16, ty = tid / 16;

    __shared__ float a_sm[32 * 65];
    __shared__ float b_sm[64 * 68];

    float acc[2][4] = {};

    const int lr = tid / 16;
    const int lc = (tid % 16) * 4;

    for (int kt = 0; kt < DD; kt += 64) {
        {
            float4 va = *(const float4*)(X + (m0 + lr) * DD + kt + lc);
            float* d0 = a_sm + lr * 65 + lc;
            d0[0] = va.x; d0[1] = va.y; d0[2] = va.z; d0[3] = va.w;
            float4 vb = *(const float4*)(X + (m0 + lr + 16) * DD + kt + lc);
            float* d1 = a_sm + (lr + 16) * 65 + lc;
            d1[0] = vb.x; d1[1] = vb.y; d1[2] = vb.z; d1[3] = vb.w;
        }
        #pragma unroll
        for (int j = 0; j < 4; j++) {
            int nr = lr + 16 * j;
            float4 vb = *(const float4*)(Wt + (n0 + nr) * DD + kt + lc);
            b_sm[(lc + 0) * 68 + nr] = vb.x;
            b_sm[(lc + 1) * 68 + nr] = vb.y;
            b_sm[(lc + 2) * 68 + nr] = vb.z;
            b_sm[(lc + 3) * 68 + nr] = vb.w;
        }
        __syncthreads();
        #pragma unroll
        for (int k = 0; k < 64; k++) {
            float a0 = a_sm[ty * 65 + k];
            float a1 = a_sm[(ty + 16) * 65 + k];
            float4 bf = *(const float4*)(b_sm + k * 68 + tx * 4);
            acc[0][0] += a0 * bf.x; acc[0][1] += a0 * bf.y; acc[0][2] += a0 * bf.z; acc[0][3] += a0 * bf.w;
            acc[1][0] += a1 * bf.x; acc[1][1] += a1 * bf.y; acc[1][2] += a1 * bf.z; acc[1][3] += a1 * bf.w;
        }
        __syncthreads();
    }

    #pragma unroll
    for (int i = 0; i < 2; i++) {
        int m = m0 + ty + 16 * i;
        int b = m / LL, l = m % LL;
        #pragma unroll
        for (int j = 0; j < 4; j++) {
            int jc = n0 + tx * 4 + j;
            float val = acc[i][j] + bias[jc];
            int h = jc / DHH, dh = jc % DHH;
            if (z == 0) {
                g_KP[((b * HH + h) * LL + l) * DHH + dh] = val;
            } else if (z == 2) {
                g_VP[((b * HH + h) * LL + l) * DHH + dh] = val;
            } else {
                g_QU[m * DD + jc] = val + u[jc];
                g_QV[m * DD + jc] = val + vvec[jc];
            }
        }
    }
}

// ---------------------------------------------------------------------------
// Kernel 2: W[b,q,h,:] = sum_dh QV[b,q,h,dh] * Wr[h*32+dh, :]
// ---------------------------------------------------------------------------
__global__ void __launch_bounds__(256) w_kernel(const float* __restrict__ Wr)
{
    const int h  = blockIdx.z;
    const int m0 = blockIdx.x * 64;
    const int n0 = blockIdx.y * 64;
    const int tid = threadIdx.x;
    const int tx = tid % 16, ty = tid / 16;

    __shared__ float a_sm[64 * 33];
    __shared__ float b_sm[32 * 68];

    {
        int r = tid / 4, cb = (tid % 4) * 8;
        #pragma unroll
        for (int cc = 0; cc < 8; cc += 4) {
            float4 va = *(const float4*)(g_QV + (m0 + r) * DD + h * DHH + cb + cc);
            float* dst = a_sm + r * 33 + cb + cc;
            dst[0] = va.x; dst[1] = va.y; dst[2] = va.z; dst[3] = va.w;
        }
    }
    {
        int k = tid / 8, cb = (tid % 8) * 8;
        #pragma unroll
        for (int cc = 0; cc < 8; cc += 4) {
            float4 vb = *(const float4*)(Wr + (h * DHH + k) * DD + n0 + cb + cc);
            *(float4*)(b_sm + k * 68 + cb + cc) = vb;
        }
    }
    __syncthreads();

    float acc[4][4] = {};
    #pragma unroll
    for (int k = 0; k < 32; k++) {
        float a0 = a_sm[(ty * 4 + 0) * 33 + k];
        float a1 = a_sm[(ty * 4 + 1) * 33 + k];
        float a2 = a_sm[(ty * 4 + 2) * 33 + k];
        float a3 = a_sm[(ty * 4 + 3) * 33 + k];
        float4 bf = *(const float4*)(b_sm + k * 68 + tx * 4);
        acc[0][0] += a0 * bf.x; acc[0][1] += a0 * bf.y; acc[0][2] += a0 * bf.z; acc[0][3] += a0 * bf.w;
        acc[1][0] += a1 * bf.x; acc[1][1] += a1 * bf.y; acc[1][2] += a1 * bf.z; acc[1][3] += a1 * bf.w;
        acc[2][0] += a2 * bf.x; acc[2][1] += a2 * bf.y; acc[2][2] += a2 * bf.z; acc[2][3] += a2 * bf.w;
        acc[3][0] += a3 * bf.x; acc[3][1] += a3 * bf.y; acc[3][2] += a3 * bf.z; acc[3][3] += a3 * bf.w;
    }

    #pragma unroll
    for (int i = 0; i < 4; i++) {
        int bq = m0 + ty * 4 + i;
        #pragma unroll
        for (int j = 0; j < 4; j++) {
            g_W[((size_t)bq * HH + h) * DD + n0 + tx * 4 + j] = acc[i][j];
        }
    }
}

// ---------------------------------------------------------------------------
// Kernel 2b: content term  AC[b,h,q,k] = sum_dh QU[b,q,h,dh] * KP[b,h,k,dh]
// per-(b,h) GEMM [384 x 32] @ [32 x 384]. 64x64 tile. grid (6, 6, 16)
// ---------------------------------------------------------------------------
__global__ void __launch_bounds__(256) ac_kernel()
{
    const int bh = blockIdx.z;
    const int b = bh / HH, h = bh % HH;
    const int q0 = blockIdx.x * 64;
    const int k0 = blockIdx.y * 64;
    const int tid = threadIdx.x;
    const int tx = tid % 16, ty = tid / 16;

    __shared__ float a_sm[64 * 33];   // [q][d]
    __shared__ float b_sm[32 * 68];   // [d][k]

    {   // A: QU rows, head slice (64 q x 32 d)
        int r = tid / 4, cb = (tid % 4) * 8;
        #pragma unroll
        for (int cc = 0; cc < 8; cc += 4) {
            float4 va = *(const float4*)(g_QU + ((b * LL + q0 + r)) * DD + h * DHH + cb + cc);
            float* dst = a_sm + r * 33 + cb + cc;
            dst[0] = va.x; dst[1] = va.y; dst[2] = va.z; dst[3] = va.w;
        }
    }
    {   // B: KP rows (64 k x 32 d), transposed into [d][k]
        int r = tid / 4, cb = (tid % 4) * 8;
        #pragma unroll
        for (int cc = 0; cc < 8; cc += 4) {
            float4 vb = *(const float4*)(g_KP + ((size_t)(b * HH + h) * LL + k0 + r) * DHH + cb + cc);
            b_sm[(cb + cc + 0) * 68 + r] = vb.x;
            b_sm[(cb + cc + 1) * 68 + r] = vb.y;
            b_sm[(cb + cc + 2) * 68 + r] = vb.z;
            b_sm[(cb + cc + 3) * 68 + r] = vb.w;
        }
    }
    __syncthreads();

    float acc[4][4] = {};
    #pragma unroll
    for (int k = 0; k < 32; k++) {
        float a0 = a_sm[(ty * 4 + 0) * 33 + k];
        float a1 = a_sm[(ty * 4 + 1) * 33 + k];
        float a2 = a_sm[(ty * 4 + 2) * 33 + k];
        float a3 = a_sm[(ty * 4 + 3) * 33 + k];
        float4 bf = *(const float4*)(b_sm + k * 68 + tx * 4);
        acc[0][0] += a0 * bf.x; acc[0][1] += a0 * bf.y; acc[0][2] += a0 * bf.z; acc[0][3] += a0 * bf.w;
        acc[1][0] += a1 * bf.x; acc[1][1] += a1 * bf.y; acc[1][2] += a1 * bf.z; acc[1][3] += a1 * bf.w;
        acc[2][0] += a2 * bf.x; acc[2][1] += a2 * bf.y; acc[2][2] += a2 * bf.z; acc[2][3] += a2 * bf.w;
        acc[3][0] += a3 * bf.x; acc[3][1] += a3 * bf.y; acc[3][2] += a3 * bf.z; acc[3][3] += a3 * bf.w;
    }

    #pragma unroll
    for (int i = 0; i < 4; i++) {
        int qg = q0 + ty * 4 + i;
        #pragma unroll
        for (int j = 0; j < 4; j++) {
            g_AC[((size_t)bh * LL + qg) * LL + k0 + tx * 4 + j] = acc[i][j];
        }
    }
}

// ---------------------------------------------------------------------------
// Kernel 3: attention. Block per (q,b). Phase 1: each pos element read ONCE.
// Thread (lane=k-in-tile, warp=d-group of 32): loads pos float4 once, 8 FMA4
// against W broadcasts (all 8 heads). Cross-warp combine via smem reduction.
// cp.async double-buffered staging. Phase 2: warp=head softmax + attn@V.
// ---------------------------------------------------------------------------
// dynamic smem layout (floats)
#define SM_POS  0
#define SM_RED  (2*KT*PSTR)            // 16640
#define SM_W    (SM_RED + HH*HH*KT)    // +2048
#define SM_SC   (SM_W + HH*DD)         // +2048
#define SM_PM   (SM_SC + HH*LL)        // +3072
#define SM_CCP  (SM_PM + LL)           // +384
#define SM_TOT  (SM_CCP + 16)
#define SMEM_BYTES (SM_TOT * 4)

__global__ void __launch_bounds__(256) attn_kernel(
    const float* __restrict__ pos,
    const float* __restrict__ key_mask,
    const float* __restrict__ br,
    float* __restrict__ out)
{
    extern __shared__ __align__(16) float smem[];
    const int q = blockIdx.x, b = blockIdx.y;
    const int tid = threadIdx.x;
    const int lane = tid & 31;
    const int wid = tid >> 5;   // phase 1: d-group; phase 2: head

    const float* posb = pos + ((size_t)(b * LL + q)) * LL * DD;

    // prologue: stage tile 0
    {
        const float4* src = (const float4*)posb;
        uint32_t dst0 = (uint32_t)__cvta_generic_to_shared(smem + SM_POS);
        #pragma unroll
        for (int i = 0; i < 8; i++) {
            int idx = tid + i * 256;
            int row = idx >> 6, d4 = idx & 63;
            asm volatile("cp.async.cg.shared.global [%0], [%1], 16;\n"
                         :: "r"(dst0 + (uint32_t)(row * 65 + d4) * 16), "l"(src + idx));
        }
        asm volatile("cp.async.commit_group;\n");
    }

    // init: W slice, mask penalty, ccp
    {
        const float4* wsrc = (const float4*)(g_W + ((size_t)(b * LL + q)) * HH * DD);
        float4* wdst = (float4*)(smem + SM_W);
        wdst[tid]       = wsrc[tid];
        wdst[tid + 256] = wsrc[tid + 256];
    }
    for (int k = tid; k < LL; k += 256)
        smem[SM_PM + k] = (1.0f - key_mask[b * LL + k]) * 1e15f;
    {
        float c = g_QV[(b * LL + q) * DD + wid * DHH + lane] * br[wid * DHH + lane];
        #pragma unroll
        for (int off = 16; off; off >>= 1)
            c += __shfl_xor_sync(0xffffffffu, c, off);
        if (lane == 0) smem[SM_CCP + wid] = c;
    }

    const float scale = 0.17677669529663687f;  // 1/sqrt(32)
    const float* acrow = g_AC + ((size_t)(b * HH + wid) * LL + q) * LL;

    for (int t = 0; t < NT; t++) {
        if (t + 1 < NT) {
            const float4* src = (const float4*)(posb + (size_t)(t + 1) * KT * DD);
            uint32_t dstb = (uint32_t)__cvta_generic_to_shared(smem + SM_POS + ((t + 1) & 1) * KT * PSTR);
            #pragma unroll
            for (int i = 0; i < 8; i++) {
                int idx = tid + i * 256;
                int row = idx >> 6, d4 = idx & 63;
                asm volatile("cp.async.cg.shared.global [%0], [%1], 16;\n"
                             :: "r"(dstb + (uint32_t)(row * 65 + d4) * 16), "l"(src + idx));
            }
            asm volatile("cp.async.commit_group;\n");
            asm volatile("cp.async.wait_group 1;\n");
        } else {
            asm volatile("cp.async.wait_group 0;\n");
        }
        __syncthreads();

        // partial dot: thread (k=lane, dgroup=wid) over its 32-d slice, all 8 heads
        float acc[8] = {0.f, 0.f, 0.f, 0.f, 0.f, 0.f, 0.f, 0.f};
        const float* prow = smem + SM_POS + (t & 1) * KT * PSTR + lane * PSTR + wid * 32;
        #pragma unroll
        for (int d4 = 0; d4 < 8; d4++) {
            float4 p = *(const float4*)(prow + d4 * 4);
            #pragma unroll
            for (int h = 0; h < 8; h++) {
                float4 w = *(const float4*)(smem + SM_W + h * DD + wid * 32 + d4 * 4);
                acc[h] = fmaf(p.x, w.x, fmaf(p.y, w.y, fmaf(p.z, w.z, fmaf(p.w, w.w, acc[h]))));
            }
        }
        #pragma unroll
        for (int h = 0; h < 8; h++)
            smem[SM_RED + (wid * 8 + h) * KT + lane] = acc[h];
        __syncthreads();

        // reduce across the 8 d-groups; warp wid acts as head
        {
            float s = 0.f;
            #pragma unroll
            for (int dg = 0; dg < 8; dg++)
                s += smem[SM_RED + (dg * 8 + wid) * KT + lane];
            int kg = t * KT + lane;
            s += acrow[kg];                       // content term A+C
            smem[SM_SC + wid * LL + kg] = (s + smem[SM_CCP + wid]) * scale - smem[SM_PM + kg];
        }
        __syncthreads();
    }

    // phase 2: softmax per head (warp = head)
    float* scrow = smem + SM_SC + wid * LL;
    float m = -1e30f;
    for (int k = lane; k < LL; k += 32) m = fmaxf(m, scrow[k]);
    #pragma unroll
    for (int off = 16; off; off >>= 1)
        m = fmaxf(m, __shfl_xor_sync(0xffffffffu, m, off));
    float s = 0.f;
    for (int k = lane; k < LL; k += 32) {
        float e = __expf(scrow[k] - m);
        scrow[k] = e;
        s += e;
    }
    #pragma unroll
    for (int off = 16; off; off >>= 1)
        s += __shfl_xor_sync(0xffffffffu, s, off);
    const float rinv = 1.0f / s;
    __syncwarp();

    // out = attn @ V  (lane = dh, coalesced)
    float acc = 0.f;
    const float* vp = g_VP + ((size_t)(b * HH + wid)) * LL * DHH + lane;
    #pragma unroll 4
    for (int k = 0; k < LL; k++)
        acc += scrow[k] * vp[k * DHH];

    out[(b * LL + q) * DD + wid * DHH + lane] = acc * rinv;
}

// ---------------------------------------------------------------------------
extern "C" void kernel_launch(void* const* d_in, const int* in_sizes, int n_in,
                              void* d_out, int out_size)
{
    const float* key      = (const float*)d_in[0];
    const float* query    = (const float*)d_in[1];
    const float* value    = (const float*)d_in[2];
    const float* pos      = (const float*)d_in[3];
    const float* key_mask = (const float*)d_in[4];
    const float* Wk = (const float*)d_in[5];
    const float* bk = (const float*)d_in[6];
    const float* Wq = (const float*)d_in[7];
    const float* bq = (const float*)d_in[8];
    const float* Wv = (const float*)d_in[9];
    const float* bv = (const float*)d_in[10];
    const float* Wr = (const float*)d_in[11];
    const float* br = (const float*)d_in[12];
    const float* u  = (const float*)d_in[13];
    const float* v  = (const float*)d_in[14];
    float* out = (float*)d_out;

    cudaFuncSetAttribute(attn_kernel, cudaFuncAttributeMaxDynamicSharedMemorySize, SMEM_BYTES);

    proj_kernel<<<dim3(24, 4, 3), 256>>>(key, query, value, Wk, bk, Wq, bq, Wv, bv, u, v);
    w_kernel<<<dim3(12, 4, 8), 256>>>(Wr);
    ac_kernel<<<dim3(6, 6, 16), 256>>>();
    attn_kernel<<<dim3(LL, BB), 256, SMEM_BYTES>>>(pos, key_mask, br, out);
}